// round 12
// baseline (speedup 1.0000x reference)
#include <cuda_runtime.h>
#include <cuda_bf16.h>
#include <cstdint>

#define TOK   16384
#define HDIM  1024
#define FDIM  4096
#define NEXP  8

#define BM 128
#define BN 256
#define BK 128
#define NS 2
#define A_BYTES     32768          // 128 rows x 256 B (128 bf16)
#define STAGE_BYTES 98304
#define NTHR 512

// prologue mega-kernel section sizes
#define NT1 16384                  // transpose W1 blocks (128 x 16 x 8)
#define NT2 16384                  // transpose W2 blocks (32 x 64 x 8)
#define NCT 256                    // ctotal blocks (4 x 64)
#define NLN 2048                   // ln_router blocks (TOK/8)
#define NPRO (NT1 + NT2 + NCT + NLN)
#define PRO_SMEM 41216             // max(33024+8192, 8448)

// ---------------- scratch (device globals; no runtime allocation) ----------------
__device__ __nv_bfloat16 g_xn [(size_t)TOK * HDIM];          //  34 MB
__device__ __nv_bfloat16 g_h  [(size_t)TOK * 2 * FDIM];      // 268 MB
__device__ __nv_bfloat16 g_w1t[(size_t)NEXP * FDIM * HDIM];  //  67 MB  W1^T [e][f][h] K-major
__device__ __nv_bfloat16 g_w2t[(size_t)NEXP * HDIM * FDIM];  //  67 MB  W2^T [e][h][f] K-major
__device__ float g_ctotal[HDIM];
__device__ float g_score[TOK * 2];
__device__ float g_stot[TOK];
__device__ int   g_cnt[NEXP];
__device__ int   g_elist[NEXP * TOK];

// ---------------- helpers ----------------
__device__ __forceinline__ uint32_t smem_u32(const void* p) {
    uint32_t a;
    asm("{ .reg .u64 t; cvta.to.shared.u64 t, %1; cvt.u32.u64 %0, t; }" : "=r"(a) : "l"(p));
    return a;
}
__device__ __forceinline__ void cp16(uint32_t dst, const void* src) {
    asm volatile("cp.async.cg.shared.global [%0], [%1], 16;" :: "r"(dst), "l"(src));
}
__device__ __forceinline__ void cp_commit() { asm volatile("cp.async.commit_group;"); }
template <int N> __device__ __forceinline__ void cp_wait() {
    asm volatile("cp.async.wait_group %0;" :: "n"(N));
}
__device__ __forceinline__ void ldsm4(uint32_t (&r)[4], uint32_t addr) {
    asm volatile("ldmatrix.sync.aligned.m8n8.x4.shared.b16 {%0,%1,%2,%3}, [%4];"
                 : "=r"(r[0]), "=r"(r[1]), "=r"(r[2]), "=r"(r[3]) : "r"(addr));
}
__device__ __forceinline__ void mma_bf16(float (&d)[4], const uint32_t (&a)[4],
                                         uint32_t b0, uint32_t b1) {
    asm volatile(
        "mma.sync.aligned.m16n8k16.row.col.f32.bf16.bf16.f32 "
        "{%0,%1,%2,%3}, {%4,%5,%6,%7}, {%8,%9}, {%0,%1,%2,%3};"
        : "+f"(d[0]), "+f"(d[1]), "+f"(d[2]), "+f"(d[3])
        : "r"(a[0]), "r"(a[1]), "r"(a[2]), "r"(a[3]), "r"(b0), "r"(b1));
}

// ---------------- kernel 0 ----------------
__global__ void zero_kernel() {
    int i = threadIdx.x;
    if (i < NEXP) g_cnt[i] = 0;
    g_ctotal[i] = 0.f;
}

// ---------------- fused prologue: transposes + ctotal + ln_router ----------------
__global__ void __launch_bounds__(256) prologue_kernel(
    const float* __restrict__ x, const float* __restrict__ gamma,
    const float* __restrict__ beta, const float* __restrict__ Wr,
    const float* __restrict__ br, const float* __restrict__ W1,
    const float* __restrict__ b1, const float* __restrict__ W2,
    const float* __restrict__ b2)
{
    extern __shared__ char dsm[];
    const int bid = blockIdx.x;
    const int tid = threadIdx.x;

    if (bid < NT1 + NT2) {
        // ---- weight transpose -> K-major [E][N][K], bf16 ----
        const int which = (bid < NT1) ? 0 : 1;
        const int sub = which ? (bid - NT1) : bid;
        const int R = which ? FDIM : HDIM;       // K
        const int C = which ? HDIM : FDIM;       // N
        const int GX = which ? 32 : 128;         // C/32
        const int GY = which ? 64 : 16;          // R/64
        const float* src = which ? W2 : W1;
        __nv_bfloat16* dst = which ? g_w2t : g_w1t;
        const int gx = sub % GX, gy = (sub / GX) % GY, gz = sub / (GX * GY);
        float (*t)[33] = reinterpret_cast<float (*)[33]>(dsm);
        const size_t base = (size_t)gz * R * C;
        const int c0 = gx * 32, r0 = gy * 64;
        const int tc = tid & 31, tr = tid >> 5;
        #pragma unroll
        for (int j = 0; j < 64; j += 8)
            t[tr + j][tc] = src[base + (size_t)(r0 + tr + j) * C + c0 + tc];
        __syncthreads();
        const int wk = tid & 63, wn = tid >> 6;
        __nv_bfloat16* dbase = dst + base;
        #pragma unroll
        for (int j = 0; j < 32; j += 4)
            dbase[(size_t)(c0 + wn + j) * R + r0 + wk] = __float2bfloat16_rn(t[wk][wn + j]);
        return;
    }

    if (bid < NT1 + NT2 + NCT) {
        // ---- c_total (exact fp32) ----
        const int sub = bid - (NT1 + NT2);
        const int h = (sub % 4) * 256 + tid;
        const int chunk = sub / 4;
        float acc = 0.f;
        for (int i = 0; i < 512; i++) {
            int ef = chunk * 512 + i;
            float bb = b1[ef];
            if (bb > 0.f) acc += bb * W2[(size_t)ef * HDIM + h];
        }
        if (acc != 0.f) atomicAdd(&g_ctotal[h], acc);
        if (chunk < NEXP) atomicAdd(&g_ctotal[h], b2[chunk * HDIM + h]);
        return;
    }

    // ---- LayerNorm + router: warp-per-token, Wr cached in smem ----
    {
        float* sWrT = reinterpret_cast<float*>(dsm);          // [8][1032]
        float* sg   = sWrT + NEXP * 1032;                     // [1024]
        float* sb   = sg + HDIM;                              // [1024]
        const int lane = tid & 31, wid = tid >> 5;

        for (int idx = tid; idx < HDIM * NEXP; idx += 256) {
            int h = idx >> 3, e = idx & 7;
            sWrT[e * 1032 + h] = Wr[idx];
        }
        for (int i = tid; i < HDIM / 4; i += 256) {
            ((float4*)sg)[i] = ((const float4*)gamma)[i];
            ((float4*)sb)[i] = ((const float4*)beta)[i];
        }
        __syncthreads();

        const int t = (bid - (NT1 + NT2 + NCT)) * 8 + wid;
        const float4* xr = (const float4*)(x + (size_t)t * HDIM);

        float4 xv[8];
        float s1 = 0.f, s2 = 0.f;
        #pragma unroll
        for (int j = 0; j < 8; j++) {
            xv[j] = xr[lane + 32 * j];
            s1 += xv[j].x + xv[j].y + xv[j].z + xv[j].w;
            s2 += xv[j].x*xv[j].x + xv[j].y*xv[j].y + xv[j].z*xv[j].z + xv[j].w*xv[j].w;
        }
        #pragma unroll
        for (int o = 16; o; o >>= 1) {
            s1 += __shfl_xor_sync(0xffffffffu, s1, o);
            s2 += __shfl_xor_sync(0xffffffffu, s2, o);
        }
        const float mu = s1 * (1.f / HDIM);
        const float var = s2 * (1.f / HDIM) - mu * mu;
        const float rs = rsqrtf(var + 1e-5f);

        #pragma unroll
        for (int j = 0; j < 8; j++) {
            const float4 g  = ((const float4*)sg)[lane + 32 * j];
            const float4 be = ((const float4*)sb)[lane + 32 * j];
            xv[j].x = (xv[j].x - mu) * rs * g.x + be.x;
            xv[j].y = (xv[j].y - mu) * rs * g.y + be.y;
            xv[j].z = (xv[j].z - mu) * rs * g.z + be.z;
            xv[j].w = (xv[j].w - mu) * rs * g.w + be.w;
            __nv_bfloat162 h01 = __floats2bfloat162_rn(xv[j].x, xv[j].y);
            __nv_bfloat162 h23 = __floats2bfloat162_rn(xv[j].z, xv[j].w);
            uint2 pk = make_uint2(*(uint32_t*)&h01, *(uint32_t*)&h23);
            *(uint2*)(g_xn + (size_t)t * HDIM + (lane + 32 * j) * 4) = pk;
        }

        float lg[NEXP];
        #pragma unroll
        for (int e = 0; e < NEXP; e++) {
            const float4* we = (const float4*)(sWrT + e * 1032);
            float acc = 0.f;
            #pragma unroll
            for (int j = 0; j < 8; j++) {
                const float4 w = we[lane + 32 * j];
                acc += xv[j].x*w.x + xv[j].y*w.y + xv[j].z*w.z + xv[j].w*w.w;
            }
            lg[e] = acc;
        }
        #pragma unroll
        for (int e = 0; e < NEXP; e++)
            #pragma unroll
            for (int o = 16; o; o >>= 1)
                lg[e] += __shfl_xor_sync(0xffffffffu, lg[e], o);

        if (lane == 0) {
            float L[NEXP];
            #pragma unroll
            for (int e = 0; e < NEXP; e++) L[e] = lg[e] + br[e];
            float mx = L[0];
            #pragma unroll
            for (int e = 1; e < NEXP; e++) mx = fmaxf(mx, L[e]);
            float ex[NEXP], den = 0.f;
            #pragma unroll
            for (int e = 0; e < NEXP; e++) { ex[e] = __expf(L[e] - mx); den += ex[e]; }
            int i0 = 0;
            #pragma unroll
            for (int e = 1; e < NEXP; e++) if (L[e] > L[i0]) i0 = e;
            int i1 = (i0 == 0) ? 1 : 0;
            #pragma unroll
            for (int e = 0; e < NEXP; e++) if (e != i0 && L[e] > L[i1]) i1 = e;
            float inv = 1.f / den;
            float sc0 = ex[i0] * inv, sc1 = ex[i1] * inv;
            g_score[2*t] = sc0; g_score[2*t+1] = sc1;
            g_stot[t] = sc0 + sc1;
            int p0 = atomicAdd(&g_cnt[i0], 1); g_elist[i0 * TOK + p0] = 2*t;
            int p1 = atomicAdd(&g_cnt[i1], 1); g_elist[i1 * TOK + p1] = 2*t + 1;
        }
    }
}

// ---------------- init: out = x + stot * c_total ----------------
__global__ void __launch_bounds__(256) init_out_kernel(const float* __restrict__ x,
                                                       float* __restrict__ out) {
    const int t = blockIdx.x;
    const int tid = threadIdx.x;
    const float st = g_stot[t];
    const float4 xv = ((const float4*)(x + (size_t)t * HDIM))[tid];
    const float4 ct = ((const float4*)g_ctotal)[tid];
    float4 o;
    o.x = xv.x + st * ct.x;
    o.y = xv.y + st * ct.y;
    o.z = xv.z + st * ct.z;
    o.w = xv.w + st * ct.w;
    ((float4*)(out + (size_t)t * HDIM))[tid] = o;
}

// ---------------- bf16 mma.sync GEMM: BK=128, NS=2, 512 threads, 16 warps (2m x 8n) ----------------
// MODE 1: g_h[off+row] = bf16( relu(xn@W1+b1) - relu(b1) )   K=1024, N=4096
// MODE 2: out[token]  += score * (g_h @ W2)  (atomic)        K=4096, N=1024
template <int MODE>
__global__ void __launch_bounds__(NTHR, 1) mm_gemm(const float* __restrict__ bias,
                                                   float* __restrict__ out) {
    constexpr int KD  = (MODE == 1) ? HDIM : FDIM;
    constexpr int ND  = (MODE == 1) ? FDIM : HDIM;
    constexpr int NKT = KD / BK;

    const int e = blockIdx.z;
    const int cnt = g_cnt[e];
    const int mb0 = blockIdx.y * BM;
    if (mb0 >= cnt) return;
    const int nb = blockIdx.x * BN;

    int off = 0;
    #pragma unroll
    for (int i = 0; i < NEXP; i++) off += (i < e) ? g_cnt[i] : 0;

    extern __shared__ char dyn[];
    __shared__ int   s_rowoff[BM];
    __shared__ int   s_tok[BM];
    __shared__ float s_sc[BM];

    const int tid = threadIdx.x;
    const int lane = tid & 31, wid = tid >> 5;
    const uint32_t sbase = smem_u32(dyn);

    if (tid < BM) {
        int r = mb0 + tid;
        int rc = (r < cnt) ? r : (cnt - 1);
        int ent = g_elist[e * TOK + rc];
        if (MODE == 1) {
            s_rowoff[tid] = (ent >> 1) * HDIM;
        } else {
            s_rowoff[tid] = (off + rc) * FDIM;
            s_tok[tid] = ent >> 1;
            s_sc[tid]  = g_score[ent];
        }
    }
    __syncthreads();

    const __nv_bfloat16* Ag = (MODE == 1) ? g_xn : g_h;
    const __nv_bfloat16* Bg = ((MODE == 1) ? g_w1t : g_w2t) + (size_t)(e * ND + nb) * KD;

    const int grow = tid >> 4;
    const int gc   = tid & 15;

    auto load_stage = [&](int kt) {
        const uint32_t sa = sbase + (kt & 1) * STAGE_BYTES;
        const int k0 = kt * BK;
        #pragma unroll
        for (int i = 0; i < 4; i++) {
            const int ar = grow + i * 32;
            cp16(sa + ar * 256 + ((gc ^ (ar & 7)) << 4),
                 Ag + (size_t)s_rowoff[ar] + k0 + gc * 8);
        }
        const uint32_t sb = sa + A_BYTES;
        #pragma unroll
        for (int i = 0; i < 8; i++) {
            const int br = grow + i * 32;
            cp16(sb + br * 256 + ((gc ^ (br & 7)) << 4),
                 Bg + (size_t)br * KD + k0 + gc * 8);
        }
    };

    const int wm = wid & 1, wn = wid >> 1;
    const int jj = lane >> 3, ii = lane & 7;
    const int rA  = (jj & 1) * 8 + ii;
    const int chA = jj >> 1;
    const int rB  = (jj >> 1) * 8 + ii;
    const int chB = jj & 1;

    float acc[4][4][4];
    #pragma unroll
    for (int i = 0; i < 4; i++)
        #pragma unroll
        for (int j = 0; j < 4; j++)
            #pragma unroll
            for (int c = 0; c < 4; c++) acc[i][j][c] = 0.f;

    load_stage(0); cp_commit();

    #pragma unroll 1
    for (int kt = 0; kt < NKT; kt++) {
        cp_wait<0>();
        __syncthreads();
        const int nl = kt + 1;
        if (nl < NKT) load_stage(nl);
        cp_commit();

        const uint32_t sa = sbase + (kt & 1) * STAGE_BYTES;
        const uint32_t aw = sa + (wm * 64 + rA) * 256;
        const uint32_t bw = sa + A_BYTES + (wn * 32 + rB) * 256;
        const int sxA = ii;
        const int sxB = ii;
        #pragma unroll
        for (int ks = 0; ks < 8; ks++) {
            uint32_t af[4][4];
            #pragma unroll
            for (int mb = 0; mb < 4; mb++)
                ldsm4(af[mb], aw + mb * 4096 + (((2*ks + chA) ^ sxA) << 4));
            uint32_t bf[2][4];
            #pragma unroll
            for (int np = 0; np < 2; np++)
                ldsm4(bf[np], bw + np * 4096 + (((2*ks + chB) ^ sxB) << 4));
            #pragma unroll
            for (int mb = 0; mb < 4; mb++)
                #pragma unroll
                for (int np = 0; np < 2; np++) {
                    mma_bf16(acc[mb][np*2+0], af[mb], bf[np][0], bf[np][1]);
                    mma_bf16(acc[mb][np*2+1], af[mb], bf[np][2], bf[np][3]);
                }
        }
    }

    // ---------------- epilogue ----------------
    const int qr = lane >> 2;
    const int qc = (lane & 3) * 2;
    #pragma unroll
    for (int mb = 0; mb < 4; mb++) {
        #pragma unroll
        for (int half = 0; half < 2; half++) {
            const int rloc = wm * 64 + mb * 16 + qr + half * 8;
            if (mb0 + rloc >= cnt) continue;
            #pragma unroll
            for (int nblk = 0; nblk < 4; nblk++) {
                const int cg = nb + wn * 32 + nblk * 8 + qc;
                float v0 = acc[mb][nblk][half * 2 + 0];
                float v1 = acc[mb][nblk][half * 2 + 1];
                if (MODE == 1) {
                    const float2 bb = *(const float2*)(bias + e * FDIM + cg);
                    v0 = fmaxf(v0 + bb.x, 0.f) - fmaxf(bb.x, 0.f);
                    v1 = fmaxf(v1 + bb.y, 0.f) - fmaxf(bb.y, 0.f);
                    __nv_bfloat162 pk = __floats2bfloat162_rn(v0, v1);
                    *(uint32_t*)(g_h + (size_t)(off + mb0 + rloc) * FDIM + cg) = *(uint32_t*)&pk;
                } else {
                    const float s = s_sc[rloc];
                    float* orow = out + (size_t)s_tok[rloc] * HDIM + cg;
                    atomicAdd(orow,     s * v0);
                    atomicAdd(orow + 1, s * v1);
                }
            }
        }
    }
}

// ---------------- launch ----------------
extern "C" void kernel_launch(void* const* d_in, const int* in_sizes, int n_in,
                              void* d_out, int out_size) {
    (void)in_sizes; (void)n_in; (void)out_size;
    const float* x     = (const float*)d_in[0];
    const float* gamma = (const float*)d_in[1];
    const float* beta  = (const float*)d_in[2];
    const float* Wr    = (const float*)d_in[3];
    const float* br    = (const float*)d_in[4];
    const float* W1    = (const float*)d_in[5];
    const float* b1    = (const float*)d_in[6];
    const float* W2    = (const float*)d_in[7];
    const float* b2    = (const float*)d_in[8];
    float* out = (float*)d_out;

    const int smem = NS * STAGE_BYTES;   // 196608 B
    cudaFuncSetAttribute(mm_gemm<1>, cudaFuncAttributeMaxDynamicSharedMemorySize, smem);
    cudaFuncSetAttribute(mm_gemm<2>, cudaFuncAttributeMaxDynamicSharedMemorySize, smem);

    zero_kernel<<<1, 1024>>>();
    prologue_kernel<<<NPRO, 256, PRO_SMEM>>>(x, gamma, beta, Wr, br, W1, b1, W2, b2);
    init_out_kernel<<<TOK, 256>>>(x, out);
    mm_gemm<1><<<dim3(FDIM / BN, (2 * TOK) / BM, NEXP), NTHR, smem>>>(b1, nullptr);
    mm_gemm<2><<<dim3(HDIM / BN, (2 * TOK) / BM, NEXP), NTHR, smem>>>(nullptr, out);
}

// round 15
// speedup vs baseline: 1.0287x; 1.0287x over previous
#include <cuda_runtime.h>
#include <cuda_bf16.h>
#include <cstdint>

#define TOK   16384
#define HDIM  1024
#define FDIM  4096
#define NEXP  8

#define BM 128
#define BN 128
#define BK 64
#define NS 3
#define A_BYTES     16384          // 128 rows x 128 B (64 bf16)
#define STAGE_BYTES 32768
#define NTHR 256

// prologue mega-kernel section sizes
#define NT1 16384                  // transpose W1 blocks (128 x 16 x 8)
#define NT2 16384                  // transpose W2 blocks (32 x 64 x 8)
#define NCT 256                    // ctotal blocks (4 x 64)
#define NLN 2048                   // ln_router blocks (TOK/8)
#define NPRO (NT1 + NT2 + NCT + NLN)
#define PRO_SMEM 41216

// ---------------- scratch (device globals; no runtime allocation) ----------------
__device__ __nv_bfloat16 g_xn [(size_t)TOK * HDIM];          //  34 MB
__device__ __nv_bfloat16 g_h  [(size_t)TOK * 2 * FDIM];      // 268 MB
__device__ __nv_bfloat16 g_w1t[(size_t)NEXP * FDIM * HDIM];  //  67 MB  W1^T [e][f][h] K-major
__device__ __nv_bfloat16 g_w2t[(size_t)NEXP * HDIM * FDIM];  //  67 MB  W2^T [e][h][f] K-major
__device__ float g_ctotal[HDIM];
__device__ float g_score[TOK * 2];
__device__ float g_stot[TOK];
__device__ int   g_cnt[NEXP];
__device__ int   g_elist[NEXP * TOK];

// ---------------- helpers ----------------
__device__ __forceinline__ uint32_t smem_u32(const void* p) {
    uint32_t a;
    asm("{ .reg .u64 t; cvta.to.shared.u64 t, %1; cvt.u32.u64 %0, t; }" : "=r"(a) : "l"(p));
    return a;
}
__device__ __forceinline__ void cp16(uint32_t dst, const void* src) {
    asm volatile("cp.async.cg.shared.global [%0], [%1], 16;" :: "r"(dst), "l"(src));
}
__device__ __forceinline__ void cp_commit() { asm volatile("cp.async.commit_group;"); }
template <int N> __device__ __forceinline__ void cp_wait() {
    asm volatile("cp.async.wait_group %0;" :: "n"(N));
}
__device__ __forceinline__ void ldsm4(uint32_t (&r)[4], uint32_t addr) {
    asm volatile("ldmatrix.sync.aligned.m8n8.x4.shared.b16 {%0,%1,%2,%3}, [%4];"
                 : "=r"(r[0]), "=r"(r[1]), "=r"(r[2]), "=r"(r[3]) : "r"(addr));
}
__device__ __forceinline__ void mma_bf16(float (&d)[4], const uint32_t (&a)[4],
                                         uint32_t b0, uint32_t b1) {
    asm volatile(
        "mma.sync.aligned.m16n8k16.row.col.f32.bf16.bf16.f32 "
        "{%0,%1,%2,%3}, {%4,%5,%6,%7}, {%8,%9}, {%0,%1,%2,%3};"
        : "+f"(d[0]), "+f"(d[1]), "+f"(d[2]), "+f"(d[3])
        : "r"(a[0]), "r"(a[1]), "r"(a[2]), "r"(a[3]), "r"(b0), "r"(b1));
}

// ---------------- kernel 0 ----------------
__global__ void zero_kernel() {
    int i = threadIdx.x;
    if (i < NEXP) g_cnt[i] = 0;
    g_ctotal[i] = 0.f;
}

// ---------------- fused prologue: transposes + ctotal + ln_router ----------------
__global__ void __launch_bounds__(256) prologue_kernel(
    const float* __restrict__ x, const float* __restrict__ gamma,
    const float* __restrict__ beta, const float* __restrict__ Wr,
    const float* __restrict__ br, const float* __restrict__ W1,
    const float* __restrict__ b1, const float* __restrict__ W2,
    const float* __restrict__ b2)
{
    extern __shared__ char dsm[];
    const int bid = blockIdx.x;
    const int tid = threadIdx.x;

    if (bid < NT1 + NT2) {
        const int which = (bid < NT1) ? 0 : 1;
        const int sub = which ? (bid - NT1) : bid;
        const int R = which ? FDIM : HDIM;
        const int C = which ? HDIM : FDIM;
        const int GX = which ? 32 : 128;
        const int GY = which ? 64 : 16;
        const float* src = which ? W2 : W1;
        __nv_bfloat16* dst = which ? g_w2t : g_w1t;
        const int gx = sub % GX, gy = (sub / GX) % GY, gz = sub / (GX * GY);
        float (*t)[33] = reinterpret_cast<float (*)[33]>(dsm);
        const size_t base = (size_t)gz * R * C;
        const int c0 = gx * 32, r0 = gy * 64;
        const int tc = tid & 31, tr = tid >> 5;
        #pragma unroll
        for (int j = 0; j < 64; j += 8)
            t[tr + j][tc] = src[base + (size_t)(r0 + tr + j) * C + c0 + tc];
        __syncthreads();
        const int wk = tid & 63, wn = tid >> 6;
        __nv_bfloat16* dbase = dst + base;
        #pragma unroll
        for (int j = 0; j < 32; j += 4)
            dbase[(size_t)(c0 + wn + j) * R + r0 + wk] = __float2bfloat16_rn(t[wk][wn + j]);
        return;
    }

    if (bid < NT1 + NT2 + NCT) {
        const int sub = bid - (NT1 + NT2);
        const int h = (sub % 4) * 256 + tid;
        const int chunk = sub / 4;
        float acc = 0.f;
        for (int i = 0; i < 512; i++) {
            int ef = chunk * 512 + i;
            float bb = b1[ef];
            if (bb > 0.f) acc += bb * W2[(size_t)ef * HDIM + h];
        }
        if (acc != 0.f) atomicAdd(&g_ctotal[h], acc);
        if (chunk < NEXP) atomicAdd(&g_ctotal[h], b2[chunk * HDIM + h]);
        return;
    }

    {
        float* sWrT = reinterpret_cast<float*>(dsm);          // [8][1032]
        float* sg   = sWrT + NEXP * 1032;
        float* sb   = sg + HDIM;
        const int lane = tid & 31, wid = tid >> 5;

        for (int idx = tid; idx < HDIM * NEXP; idx += 256) {
            int h = idx >> 3, e = idx & 7;
            sWrT[e * 1032 + h] = Wr[idx];
        }
        for (int i = tid; i < HDIM / 4; i += 256) {
            ((float4*)sg)[i] = ((const float4*)gamma)[i];
            ((float4*)sb)[i] = ((const float4*)beta)[i];
        }
        __syncthreads();

        const int t = (bid - (NT1 + NT2 + NCT)) * 8 + wid;
        const float4* xr = (const float4*)(x + (size_t)t * HDIM);

        float4 xv[8];
        float s1 = 0.f, s2 = 0.f;
        #pragma unroll
        for (int j = 0; j < 8; j++) {
            xv[j] = xr[lane + 32 * j];
            s1 += xv[j].x + xv[j].y + xv[j].z + xv[j].w;
            s2 += xv[j].x*xv[j].x + xv[j].y*xv[j].y + xv[j].z*xv[j].z + xv[j].w*xv[j].w;
        }
        #pragma unroll
        for (int o = 16; o; o >>= 1) {
            s1 += __shfl_xor_sync(0xffffffffu, s1, o);
            s2 += __shfl_xor_sync(0xffffffffu, s2, o);
        }
        const float mu = s1 * (1.f / HDIM);
        const float var = s2 * (1.f / HDIM) - mu * mu;
        const float rs = rsqrtf(var + 1e-5f);

        #pragma unroll
        for (int j = 0; j < 8; j++) {
            const float4 g  = ((const float4*)sg)[lane + 32 * j];
            const float4 be = ((const float4*)sb)[lane + 32 * j];
            xv[j].x = (xv[j].x - mu) * rs * g.x + be.x;
            xv[j].y = (xv[j].y - mu) * rs * g.y + be.y;
            xv[j].z = (xv[j].z - mu) * rs * g.z + be.z;
            xv[j].w = (xv[j].w - mu) * rs * g.w + be.w;
            __nv_bfloat162 h01 = __floats2bfloat162_rn(xv[j].x, xv[j].y);
            __nv_bfloat162 h23 = __floats2bfloat162_rn(xv[j].z, xv[j].w);
            uint2 pk = make_uint2(*(uint32_t*)&h01, *(uint32_t*)&h23);
            *(uint2*)(g_xn + (size_t)t * HDIM + (lane + 32 * j) * 4) = pk;
        }

        float lg[NEXP];
        #pragma unroll
        for (int e = 0; e < NEXP; e++) {
            const float4* we = (const float4*)(sWrT + e * 1032);
            float acc = 0.f;
            #pragma unroll
            for (int j = 0; j < 8; j++) {
                const float4 w = we[lane + 32 * j];
                acc += xv[j].x*w.x + xv[j].y*w.y + xv[j].z*w.z + xv[j].w*w.w;
            }
            lg[e] = acc;
        }
        #pragma unroll
        for (int e = 0; e < NEXP; e++)
            #pragma unroll
            for (int o = 16; o; o >>= 1)
                lg[e] += __shfl_xor_sync(0xffffffffu, lg[e], o);

        if (lane == 0) {
            float L[NEXP];
            #pragma unroll
            for (int e = 0; e < NEXP; e++) L[e] = lg[e] + br[e];
            float mx = L[0];
            #pragma unroll
            for (int e = 1; e < NEXP; e++) mx = fmaxf(mx, L[e]);
            float ex[NEXP], den = 0.f;
            #pragma unroll
            for (int e = 0; e < NEXP; e++) { ex[e] = __expf(L[e] - mx); den += ex[e]; }
            int i0 = 0;
            #pragma unroll
            for (int e = 1; e < NEXP; e++) if (L[e] > L[i0]) i0 = e;
            int i1 = (i0 == 0) ? 1 : 0;
            #pragma unroll
            for (int e = 0; e < NEXP; e++) if (e != i0 && L[e] > L[i1]) i1 = e;
            float inv = 1.f / den;
            float sc0 = ex[i0] * inv, sc1 = ex[i1] * inv;
            g_score[2*t] = sc0; g_score[2*t+1] = sc1;
            g_stot[t] = sc0 + sc1;
            int p0 = atomicAdd(&g_cnt[i0], 1); g_elist[i0 * TOK + p0] = 2*t;
            int p1 = atomicAdd(&g_cnt[i1], 1); g_elist[i1 * TOK + p1] = 2*t + 1;
        }
    }
}

// ---------------- init: out = x + stot * c_total ----------------
__global__ void __launch_bounds__(256) init_out_kernel(const float* __restrict__ x,
                                                       float* __restrict__ out) {
    const int t = blockIdx.x;
    const int tid = threadIdx.x;
    const float st = g_stot[t];
    const float4 xv = ((const float4*)(x + (size_t)t * HDIM))[tid];
    const float4 ct = ((const float4*)g_ctotal)[tid];
    float4 o;
    o.x = xv.x + st * ct.x;
    o.y = xv.y + st * ct.y;
    o.z = xv.z + st * ct.z;
    o.w = xv.w + st * ct.w;
    ((float4*)(out + (size_t)t * HDIM))[tid] = o;
}

// ---------------- bf16 mma.sync GEMM: BM=128, BN=128, BK=64, NS=3, 256 thr, 2 CTAs/SM ----------------
// smem rows 128 B (8 x 16B chunks), swizzle: chunk ^= (row & 7)
// MODE 1: g_h[off+row] = bf16( relu(xn@W1+b1) - relu(b1) )   K=1024, N=4096
// MODE 2: out[token]  += score * (g_h @ W2)  (atomic)        K=4096, N=1024
template <int MODE>
__global__ void __launch_bounds__(NTHR, 2) mm_gemm(const float* __restrict__ bias,
                                                   float* __restrict__ out) {
    constexpr int KD  = (MODE == 1) ? HDIM : FDIM;
    constexpr int ND  = (MODE == 1) ? FDIM : HDIM;
    constexpr int NKT = KD / BK;

    const int e = blockIdx.z;
    const int cnt = g_cnt[e];
    const int mb0 = blockIdx.y * BM;
    if (mb0 >= cnt) return;
    const int nb = blockIdx.x * BN;

    int off = 0;
    #pragma unroll
    for (int i = 0; i < NEXP; i++) off += (i < e) ? g_cnt[i] : 0;

    extern __shared__ char dyn[];
    __shared__ int   s_rowoff[BM];
    __shared__ int   s_tok[BM];
    __shared__ float s_sc[BM];

    const int tid = threadIdx.x;
    const int lane = tid & 31, wid = tid >> 5;
    const uint32_t sbase = smem_u32(dyn);

    if (tid < BM) {
        int r = mb0 + tid;
        int rc = (r < cnt) ? r : (cnt - 1);
        int ent = g_elist[e * TOK + rc];
        if (MODE == 1) {
            s_rowoff[tid] = (ent >> 1) * HDIM;
        } else {
            s_rowoff[tid] = (off + rc) * FDIM;
            s_tok[tid] = ent >> 1;
            s_sc[tid]  = g_score[ent];
        }
    }
    __syncthreads();

    const __nv_bfloat16* Ag = (MODE == 1) ? g_xn : g_h;
    const __nv_bfloat16* Bg = ((MODE == 1) ? g_w1t : g_w2t) + (size_t)(e * ND + nb) * KD;

    // cp.async: row = tid>>3 (0..31), chunk = tid&7; A rows +{0,32,64,96}, B same
    const int grow = tid >> 3;
    const int gc   = tid & 7;

    auto load_stage = [&](int kt) {
        const uint32_t sa = sbase + (kt % NS) * STAGE_BYTES;
        const int k0 = kt * BK;
        #pragma unroll
        for (int i = 0; i < 4; i++) {
            const int ar = grow + i * 32;
            cp16(sa + ar * 128 + ((gc ^ (ar & 7)) << 4),
                 Ag + (size_t)s_rowoff[ar] + k0 + gc * 8);
        }
        const uint32_t sb = sa + A_BYTES;
        #pragma unroll
        for (int i = 0; i < 4; i++) {
            const int br = grow + i * 32;
            cp16(sb + br * 128 + ((gc ^ (br & 7)) << 4),
                 Bg + (size_t)br * KD + k0 + gc * 8);
        }
    };

    // warp layout: 2 (m) x 4 (n); warp tile 64 x 32
    const int wm = wid & 1, wn = wid >> 1;
    const int jj = lane >> 3, ii = lane & 7;
    const int rA  = (jj & 1) * 8 + ii;
    const int chA = jj >> 1;
    const int rB  = (jj >> 1) * 8 + ii;
    const int chB = jj & 1;

    float acc[4][4][4];
    #pragma unroll
    for (int i = 0; i < 4; i++)
        #pragma unroll
        for (int j = 0; j < 4; j++)
            #pragma unroll
            for (int c = 0; c < 4; c++) acc[i][j][c] = 0.f;

    load_stage(0); cp_commit();
    load_stage(1); cp_commit();

    #pragma unroll 1
    for (int kt = 0; kt < NKT; kt++) {
        cp_wait<NS - 2>();
        __syncthreads();
        const int nl = kt + NS - 1;
        if (nl < NKT) load_stage(nl);
        cp_commit();

        const uint32_t sa = sbase + (kt % NS) * STAGE_BYTES;
        const uint32_t aw = sa + (wm * 64 + rA) * 128;
        const uint32_t bw = sa + A_BYTES + (wn * 32 + rB) * 128;
        const int sxA = ii;
        const int sxB = ii;
        #pragma unroll
        for (int ks = 0; ks < 4; ks++) {
            uint32_t af[4][4];
            #pragma unroll
            for (int mb = 0; mb < 4; mb++)
                ldsm4(af[mb], aw + mb * 2048 + (((2*ks + chA) ^ sxA) << 4));
            uint32_t bf[2][4];
            #pragma unroll
            for (int np = 0; np < 2; np++)
                ldsm4(bf[np], bw + np * 2048 + (((2*ks + chB) ^ sxB) << 4));
            #pragma unroll
            for (int mb = 0; mb < 4; mb++)
                #pragma unroll
                for (int np = 0; np < 2; np++) {
                    mma_bf16(acc[mb][np*2+0], af[mb], bf[np][0], bf[np][1]);
                    mma_bf16(acc[mb][np*2+1], af[mb], bf[np][2], bf[np][3]);
                }
        }
    }

    // ---------------- epilogue ----------------
    const int qr = lane >> 2;
    const int qc = (lane & 3) * 2;
    #pragma unroll
    for (int mb = 0; mb < 4; mb++) {
        #pragma unroll
        for (int half = 0; half < 2; half++) {
            const int rloc = wm * 64 + mb * 16 + qr + half * 8;
            if (mb0 + rloc >= cnt) continue;
            #pragma unroll
            for (int nblk = 0; nblk < 4; nblk++) {
                const int cg = nb + wn * 32 + nblk * 8 + qc;
                float v0 = acc[mb][nblk][half * 2 + 0];
                float v1 = acc[mb][nblk][half * 2 + 1];
                if (MODE == 1) {
                    const float2 bb = *(const float2*)(bias + e * FDIM + cg);
                    v0 = fmaxf(v0 + bb.x, 0.f) - fmaxf(bb.x, 0.f);
                    v1 = fmaxf(v1 + bb.y, 0.f) - fmaxf(bb.y, 0.f);
                    __nv_bfloat162 pk = __floats2bfloat162_rn(v0, v1);
                    *(uint32_t*)(g_h + (size_t)(off + mb0 + rloc) * FDIM + cg) = *(uint32_t*)&pk;
                } else {
                    const float s = s_sc[rloc];
                    float* orow = out + (size_t)s_tok[rloc] * HDIM + cg;
                    atomicAdd(orow,     s * v0);
                    atomicAdd(orow + 1, s * v1);
                }
            }
        }
    }
}

// ---------------- launch ----------------
extern "C" void kernel_launch(void* const* d_in, const int* in_sizes, int n_in,
                              void* d_out, int out_size) {
    (void)in_sizes; (void)n_in; (void)out_size;
    const float* x     = (const float*)d_in[0];
    const float* gamma = (const float*)d_in[1];
    const float* beta  = (const float*)d_in[2];
    const float* Wr    = (const float*)d_in[3];
    const float* br    = (const float*)d_in[4];
    const float* W1    = (const float*)d_in[5];
    const float* b1    = (const float*)d_in[6];
    const float* W2    = (const float*)d_in[7];
    const float* b2    = (const float*)d_in[8];
    float* out = (float*)d_out;

    const int smem = NS * STAGE_BYTES;   // 98304 B per CTA
    cudaFuncSetAttribute(mm_gemm<1>, cudaFuncAttributeMaxDynamicSharedMemorySize, smem);
    cudaFuncSetAttribute(mm_gemm<2>, cudaFuncAttributeMaxDynamicSharedMemorySize, smem);

    zero_kernel<<<1, 1024>>>();
    prologue_kernel<<<NPRO, 256, PRO_SMEM>>>(x, gamma, beta, Wr, br, W1, b1, W2, b2);
    init_out_kernel<<<TOK, 256>>>(x, out);
    mm_gemm<1><<<dim3(FDIM / BN, (2 * TOK) / BM, NEXP), NTHR, smem>>>(b1, nullptr);
    mm_gemm<2><<<dim3(HDIM / BN, (2 * TOK) / BM, NEXP), NTHR, smem>>>(nullptr, out);
}